// round 1
// baseline (speedup 1.0000x reference)
#include <cuda_runtime.h>

// Composite 13-tap kernel coefficients, computed on device.
__device__ float g_comb[16];

// fd: 5 taps, gauss: 9 taps. Composite c[k] = sum_i fd[i]*gauss[k-i].
__global__ void build_composite_kernel(const float* __restrict__ fd,
                                       const float* __restrict__ gauss) {
    int k = threadIdx.x;  // 0..12
    if (k < 13) {
        float acc = 0.0f;
        #pragma unroll
        for (int i = 0; i < 5; ++i) {
            int j = k - i;
            if (j >= 0 && j < 9) acc += fd[i] * gauss[j];
        }
        g_comb[k] = acc;
    }
}

static constexpr int T_IN  = 1048576;
static constexpr int T_OUT = 1048564;            // T_IN - 12
static constexpr int ROWS  = 32;                 // 8 * 4
static constexpr int VEC_PER_ROW = T_OUT / 4;    // 262141 (T_OUT % 4 == 0)
static constexpr long TOTAL_VEC = (long)ROWS * VEC_PER_ROW;

__global__ __launch_bounds__(256)
void conv13_kernel(const float* __restrict__ x, float* __restrict__ out) {
    __shared__ float sc[13];
    if (threadIdx.x < 13) sc[threadIdx.x] = g_comb[threadIdx.x];
    __syncthreads();

    long idx = (long)blockIdx.x * blockDim.x + threadIdx.x;
    if (idx >= TOTAL_VEC) return;

    int row = (int)(idx / VEC_PER_ROW);
    int v   = (int)(idx - (long)row * VEC_PER_ROW);
    long in_off  = (long)row * T_IN  + (long)v * 4;
    long out_off = (long)row * T_OUT + (long)v * 4;

    // Need x[in_off .. in_off+15] -> 4 aligned float4 loads.
    const float4* p = reinterpret_cast<const float4*>(x + in_off);
    float4 a = p[0], b = p[1], c4 = p[2], d4 = p[3];
    float xv[16] = {a.x, a.y, a.z, a.w,
                    b.x, b.y, b.z, b.w,
                    c4.x, c4.y, c4.z, c4.w,
                    d4.x, d4.y, d4.z, d4.w};

    float y0 = 0.f, y1 = 0.f, y2 = 0.f, y3 = 0.f;
    #pragma unroll
    for (int k = 0; k < 13; ++k) {
        float c = sc[k];
        y0 = fmaf(c, xv[k],     y0);
        y1 = fmaf(c, xv[k + 1], y1);
        y2 = fmaf(c, xv[k + 2], y2);
        y3 = fmaf(c, xv[k + 3], y3);
    }

    float4 r = make_float4(y0, y1, y2, y3);
    *reinterpret_cast<float4*>(out + out_off) = r;
}

extern "C" void kernel_launch(void* const* d_in, const int* in_sizes, int n_in,
                              void* d_out, int out_size) {
    const float* x     = (const float*)d_in[0];
    const float* fd    = (const float*)d_in[1];
    const float* gauss = (const float*)d_in[2];
    float* out = (float*)d_out;

    build_composite_kernel<<<1, 32>>>(fd, gauss);

    int threads = 256;
    long blocks = (TOTAL_VEC + threads - 1) / threads;
    conv13_kernel<<<(unsigned)blocks, threads>>>(x, out);
}

// round 2
// speedup vs baseline: 1.0224x; 1.0224x over previous
#include <cuda_runtime.h>

// Composite 13-tap kernel coefficients, computed on device.
__device__ float g_comb[16];

// fd: 5 taps, gauss: 9 taps. Composite c[k] = sum_i fd[i]*gauss[k-i].
__global__ void build_composite_kernel(const float* __restrict__ fd,
                                       const float* __restrict__ gauss) {
    int k = threadIdx.x;  // 0..12
    if (k < 13) {
        float acc = 0.0f;
        #pragma unroll
        for (int i = 0; i < 5; ++i) {
            int j = k - i;
            if (j >= 0 && j < 9) acc += fd[i] * gauss[j];
        }
        g_comb[k] = acc;
    }
}

static constexpr int T_IN  = 1048576;
static constexpr int T_OUT = 1048564;            // T_IN - 12
static constexpr int ROWS  = 32;                 // 8 * 4
static constexpr int VEC_PER_ROW = T_OUT / 4;    // 262141
static constexpr long TOTAL_VEC = (long)ROWS * VEC_PER_ROW;   // 8388512 (even)
static constexpr long HALF_VEC  = TOTAL_VEC / 2;              // 4194256

__global__ __launch_bounds__(256)
void conv13_kernel(const float* __restrict__ x, float* __restrict__ out) {
    __shared__ float sc[13];
    if (threadIdx.x < 13) sc[threadIdx.x] = g_comb[threadIdx.x];
    __syncthreads();

    long gid = (long)blockIdx.x * blockDim.x + threadIdx.x;
    if (gid >= HALF_VEC) return;

    long idx1 = gid;
    long idx2 = gid + HALF_VEC;   // always < TOTAL_VEC

    int row1 = (int)(idx1 / VEC_PER_ROW);
    int v1   = (int)(idx1 - (long)row1 * VEC_PER_ROW);
    int row2 = (int)(idx2 / VEC_PER_ROW);
    int v2   = (int)(idx2 - (long)row2 * VEC_PER_ROW);

    long in1  = (long)row1 * T_IN  + (long)v1 * 4;
    long out1 = (long)row1 * T_OUT + (long)v1 * 4;
    long in2  = (long)row2 * T_IN  + (long)v2 * 4;
    long out2 = (long)row2 * T_OUT + (long)v2 * 4;

    // Front-batch all 8 independent 128-bit loads.
    const float4* p1 = reinterpret_cast<const float4*>(x + in1);
    const float4* p2 = reinterpret_cast<const float4*>(x + in2);
    float4 a0 = p1[0], a1 = p1[1], a2 = p1[2], a3 = p1[3];
    float4 b0 = p2[0], b1 = p2[1], b2 = p2[2], b3 = p2[3];

    float xa[16] = {a0.x, a0.y, a0.z, a0.w,  a1.x, a1.y, a1.z, a1.w,
                    a2.x, a2.y, a2.z, a2.w,  a3.x, a3.y, a3.z, a3.w};
    float xb[16] = {b0.x, b0.y, b0.z, b0.w,  b1.x, b1.y, b1.z, b1.w,
                    b2.x, b2.y, b2.z, b2.w,  b3.x, b3.y, b3.z, b3.w};

    float ya0 = 0.f, ya1 = 0.f, ya2 = 0.f, ya3 = 0.f;
    float yb0 = 0.f, yb1 = 0.f, yb2 = 0.f, yb3 = 0.f;
    #pragma unroll
    for (int k = 0; k < 13; ++k) {
        float c = sc[k];
        ya0 = fmaf(c, xa[k],     ya0);
        ya1 = fmaf(c, xa[k + 1], ya1);
        ya2 = fmaf(c, xa[k + 2], ya2);
        ya3 = fmaf(c, xa[k + 3], ya3);
        yb0 = fmaf(c, xb[k],     yb0);
        yb1 = fmaf(c, xb[k + 1], yb1);
        yb2 = fmaf(c, xb[k + 2], yb2);
        yb3 = fmaf(c, xb[k + 3], yb3);
    }

    *reinterpret_cast<float4*>(out + out1) = make_float4(ya0, ya1, ya2, ya3);
    *reinterpret_cast<float4*>(out + out2) = make_float4(yb0, yb1, yb2, yb3);
}

extern "C" void kernel_launch(void* const* d_in, const int* in_sizes, int n_in,
                              void* d_out, int out_size) {
    const float* x     = (const float*)d_in[0];
    const float* fd    = (const float*)d_in[1];
    const float* gauss = (const float*)d_in[2];
    float* out = (float*)d_out;

    build_composite_kernel<<<1, 32>>>(fd, gauss);

    int threads = 256;
    long blocks = (HALF_VEC + threads - 1) / threads;   // 16385
    conv13_kernel<<<(unsigned)blocks, threads>>>(x, out);
}

// round 3
// speedup vs baseline: 1.0522x; 1.0292x over previous
#include <cuda_runtime.h>

static constexpr int T_IN  = 1048576;
static constexpr int T_OUT = 1048564;            // T_IN - 12
static constexpr int ROWS  = 32;                 // 8 * 4
static constexpr int VEC_PER_ROW = T_OUT / 4;    // 262141
static constexpr long TOTAL_VEC = (long)ROWS * VEC_PER_ROW;   // 8388512 (even)
static constexpr long HALF_VEC  = TOTAL_VEC / 2;              // 4194256

__global__ __launch_bounds__(256)
void conv13_kernel(const float* __restrict__ x, float* __restrict__ out,
                   const float* __restrict__ fd, const float* __restrict__ gauss) {
    __shared__ float sc[13];
    // Compose the 13-tap kernel in-block: c[k] = sum_i fd[i]*gauss[k-i].
    if (threadIdx.x < 13) {
        int k = threadIdx.x;
        float acc = 0.0f;
        #pragma unroll
        for (int i = 0; i < 5; ++i) {
            int j = k - i;
            if (j >= 0 && j < 9) acc = fmaf(__ldg(fd + i), __ldg(gauss + j), acc);
        }
        sc[k] = acc;
    }
    __syncthreads();

    long gid = (long)blockIdx.x * blockDim.x + threadIdx.x;
    if (gid >= HALF_VEC) return;

    long idx1 = gid;
    long idx2 = gid + HALF_VEC;   // always < TOTAL_VEC

    int row1 = (int)(idx1 / VEC_PER_ROW);
    int v1   = (int)(idx1 - (long)row1 * VEC_PER_ROW);
    int row2 = (int)(idx2 / VEC_PER_ROW);
    int v2   = (int)(idx2 - (long)row2 * VEC_PER_ROW);

    long in1  = (long)row1 * T_IN  + (long)v1 * 4;
    long out1 = (long)row1 * T_OUT + (long)v1 * 4;
    long in2  = (long)row2 * T_IN  + (long)v2 * 4;
    long out2 = (long)row2 * T_OUT + (long)v2 * 4;

    // Front-batch all 8 independent 128-bit loads.
    const float4* p1 = reinterpret_cast<const float4*>(x + in1);
    const float4* p2 = reinterpret_cast<const float4*>(x + in2);
    float4 a0 = p1[0], a1 = p1[1], a2 = p1[2], a3 = p1[3];
    float4 b0 = p2[0], b1 = p2[1], b2 = p2[2], b3 = p2[3];

    float xa[16] = {a0.x, a0.y, a0.z, a0.w,  a1.x, a1.y, a1.z, a1.w,
                    a2.x, a2.y, a2.z, a2.w,  a3.x, a3.y, a3.z, a3.w};
    float xb[16] = {b0.x, b0.y, b0.z, b0.w,  b1.x, b1.y, b1.z, b1.w,
                    b2.x, b2.y, b2.z, b2.w,  b3.x, b3.y, b3.z, b3.w};

    float ya0 = 0.f, ya1 = 0.f, ya2 = 0.f, ya3 = 0.f;
    float yb0 = 0.f, yb1 = 0.f, yb2 = 0.f, yb3 = 0.f;
    #pragma unroll
    for (int k = 0; k < 13; ++k) {
        float c = sc[k];
        ya0 = fmaf(c, xa[k],     ya0);
        ya1 = fmaf(c, xa[k + 1], ya1);
        ya2 = fmaf(c, xa[k + 2], ya2);
        ya3 = fmaf(c, xa[k + 3], ya3);
        yb0 = fmaf(c, xb[k],     yb0);
        yb1 = fmaf(c, xb[k + 1], yb1);
        yb2 = fmaf(c, xb[k + 2], yb2);
        yb3 = fmaf(c, xb[k + 3], yb3);
    }

    // Streaming stores: output is never re-read.
    float4 ra = make_float4(ya0, ya1, ya2, ya3);
    float4 rb = make_float4(yb0, yb1, yb2, yb3);
    __stcs(reinterpret_cast<float4*>(out + out1), ra);
    __stcs(reinterpret_cast<float4*>(out + out2), rb);
}

extern "C" void kernel_launch(void* const* d_in, const int* in_sizes, int n_in,
                              void* d_out, int out_size) {
    const float* x     = (const float*)d_in[0];
    const float* fd    = (const float*)d_in[1];
    const float* gauss = (const float*)d_in[2];
    float* out = (float*)d_out;

    int threads = 256;
    long blocks = (HALF_VEC + threads - 1) / threads;   // 16385
    conv13_kernel<<<(unsigned)blocks, threads>>>(x, out, fd, gauss);
}

// round 4
// speedup vs baseline: 1.1429x; 1.0862x over previous
#include <cuda_runtime.h>
#include <cstdint>

static constexpr int T_IN  = 1048576;
static constexpr int T_OUT = 1048564;              // T_IN - 12
static constexpr int ROWS  = 32;                   // 8 * 4
static constexpr int VEC_PER_ROW = T_OUT / 4;      // 262141 output float4s per row
static constexpr int F4_PER_ROW  = T_IN / 4;       // 262144 input  float4s per row
static constexpr long TOTAL_F4   = (long)ROWS * F4_PER_ROW;   // 8388608
static constexpr int VEC_TILE = 512;               // output float4s per block
static constexpr int TILES_PER_ROW = 512;          // ceil(262141 / 512)
static constexpr int TILE_F4 = 515;                // input float4s needed: 512*4 + 12 floats

__global__ __launch_bounds__(256)
void conv13_tiled(const float4* __restrict__ x4, float* __restrict__ out,
                  const float* __restrict__ fd, const float* __restrict__ gauss) {
    __shared__ float4 sx[TILE_F4 + 1];
    __shared__ float sc[13];

    const int t    = threadIdx.x;
    const int row  = blockIdx.x >> 9;        // blockIdx.x / TILES_PER_ROW
    const int tile = blockIdx.x & 511;
    const int vb   = tile * VEC_TILE;        // first output vec4 of this tile (within row)

    const long gbase = (long)row * F4_PER_ROW + vb;   // first input float4 (global)

    uint32_t s0;
    asm("{ .reg .u64 a; cvta.to.shared.u64 a, %1; cvt.u32.u64 %0, a; }"
        : "=r"(s0) : "l"(sx));

    // ---- Fire-and-forget bulk load of the whole tile into smem -------------
    #pragma unroll
    for (int r = 0; r < 2; ++r) {
        int i = t + r * 256;
        long g4 = gbase + i;
        int sz = (g4 < TOTAL_F4) ? 16 : 0;   // zero-fill past end of x (last row tail)
        asm volatile("cp.async.cg.shared.global [%0], [%1], 16, %2;"
                     :: "r"(s0 + i * 16), "l"(x4 + g4), "r"(sz));
    }
    if (t < TILE_F4 - 512) {                 // i = 512..514
        int i = 512 + t;
        long g4 = gbase + i;
        int sz = (g4 < TOTAL_F4) ? 16 : 0;
        asm volatile("cp.async.cg.shared.global [%0], [%1], 16, %2;"
                     :: "r"(s0 + i * 16), "l"(x4 + g4), "r"(sz));
    }
    asm volatile("cp.async.commit_group;");

    // ---- Compose the 13-tap kernel while the copies are in flight ----------
    if (t < 13) {
        float acc = 0.0f;
        #pragma unroll
        for (int i = 0; i < 5; ++i) {
            int j = t - i;
            if (j >= 0 && j < 9) acc = fmaf(__ldg(fd + i), __ldg(gauss + j), acc);
        }
        sc[t] = acc;
    }

    asm volatile("cp.async.wait_group 0;");
    __syncthreads();

    // ---- Compute: two interleaved vec4 groups per thread -------------------
    #pragma unroll
    for (int r = 0; r < 2; ++r) {
        int v = t + r * 256;                 // local vec4 index in tile
        int gvec = vb + v;                   // vec4 index within row

        float4 q0 = sx[v], q1 = sx[v + 1], q2 = sx[v + 2], q3 = sx[v + 3];
        float xv[16] = {q0.x, q0.y, q0.z, q0.w,  q1.x, q1.y, q1.z, q1.w,
                        q2.x, q2.y, q2.z, q2.w,  q3.x, q3.y, q3.z, q3.w};

        float y0 = 0.f, y1 = 0.f, y2 = 0.f, y3 = 0.f;
        #pragma unroll
        for (int k = 0; k < 13; ++k) {
            float c = sc[k];
            y0 = fmaf(c, xv[k],     y0);
            y1 = fmaf(c, xv[k + 1], y1);
            y2 = fmaf(c, xv[k + 2], y2);
            y3 = fmaf(c, xv[k + 3], y3);
        }

        if (gvec < VEC_PER_ROW) {
            long o = (long)row * T_OUT + (long)gvec * 4;
            __stcs(reinterpret_cast<float4*>(out + o), make_float4(y0, y1, y2, y3));
        }
    }
}

extern "C" void kernel_launch(void* const* d_in, const int* in_sizes, int n_in,
                              void* d_out, int out_size) {
    const float4* x4   = (const float4*)d_in[0];
    const float* fd    = (const float*)d_in[1];
    const float* gauss = (const float*)d_in[2];
    float* out = (float*)d_out;

    dim3 grid(ROWS * TILES_PER_ROW);   // 16384 blocks
    conv13_tiled<<<grid, 256>>>(x4, out, fd, gauss);
}